// round 9
// baseline (speedup 1.0000x reference)
#include <cuda_runtime.h>
#include <cstdint>

#define NODES 336
#define NPC   8192
#define NUMCASE 2048
#define CPB 4                       // cases per CTA
#define GRID (NUMCASE / CPB)        // 512
#define MIU_F 1.9e-05f
#define ALPHA_F 0.10471975511965977f
#define QCOEF_F 73830.75f           // 0.5*1.225*ACOUSTIC^2
#define FULL 0xffffffffu

#define CRD_BYTES (2 * NODES * 2 * 4)   // 5376
#define FLD_BYTES (2 * NODES * 4 * 4)   // 10752
#define DSG_BYTES (NODES * 5 * 4)       // 6720
#define TOT_BYTES (CRD_BYTES + FLD_BYTES + DSG_BYTES)  // 22848

__device__ __forceinline__ uint32_t smem_u32(const void* p) {
    return (uint32_t)__cvta_generic_to_shared(p);
}

__global__ __launch_bounds__(128) void dyn_kernel(
    const float* __restrict__ coords,
    const float* __restrict__ fields,
    const float* __restrict__ design,
    float2* __restrict__ out)
{
    const int c0 = blockIdx.x * CPB;
    const int t = threadIdx.x;

    __shared__ alignas(16) float2 s_crd[2][2 * NODES];
    __shared__ alignas(16) float4 s_fld[2][2 * NODES];
    __shared__ alignas(16) float  s_dsg[2][NODES * 5];
    __shared__ alignas(8)  uint64_t mbar[2];
    __shared__ float s_red[2][4][4];

    if (t == 0) {
        asm volatile("mbarrier.init.shared.b64 [%0], 1;" :: "r"(smem_u32(&mbar[0])) : "memory");
        asm volatile("mbarrier.init.shared.b64 [%0], 1;" :: "r"(smem_u32(&mbar[1])) : "memory");
    }
    __syncthreads();

    // issue bulk copies for case (c0+cc) into stage st
    auto issue = [&](int st, int cc) {
        uint32_t mb = smem_u32(&mbar[st]);
        asm volatile("mbarrier.arrive.expect_tx.shared.b64 _, [%0], %1;" ::
                     "r"(mb), "r"((uint32_t)TOT_BYTES) : "memory");
        const char* g_crd = (const char*)(coords + (size_t)(c0 + cc) * NPC * 2);
        const char* g_fld = (const char*)(fields + (size_t)(c0 + cc) * NPC * 4);
        const char* g_dsg = (const char*)(design + (size_t)(c0 + cc) * NPC * 5);
        asm volatile("cp.async.bulk.shared::cta.global.mbarrier::complete_tx::bytes [%0], [%1], %2, [%3];"
                     :: "r"(smem_u32(s_crd[st])), "l"(g_crd), "r"((uint32_t)CRD_BYTES), "r"(mb) : "memory");
        asm volatile("cp.async.bulk.shared::cta.global.mbarrier::complete_tx::bytes [%0], [%1], %2, [%3];"
                     :: "r"(smem_u32(s_fld[st])), "l"(g_fld), "r"((uint32_t)FLD_BYTES), "r"(mb) : "memory");
        asm volatile("cp.async.bulk.shared::cta.global.mbarrier::complete_tx::bytes [%0], [%1], %2, [%3];"
                     :: "r"(smem_u32(s_dsg[st])), "l"(g_dsg), "r"((uint32_t)DSG_BYTES), "r"(mb) : "memory");
    };

    if (t == 0) { issue(0, 0); issue(1, 1); }   // prologue: fill both stages

    for (int it = 0; it < CPB; it++) {
        const int st = it & 1;
        const uint32_t ph = (uint32_t)((it >> 1) & 1);
        // wait stage full
        {
            uint32_t mb = smem_u32(&mbar[st]);
            uint32_t done;
            asm volatile(
                "{\n\t.reg .pred p;\n\t"
                "mbarrier.try_wait.parity.acquire.cta.shared::cta.b64 p, [%1], %2;\n\t"
                "selp.b32 %0, 1, 0, p;\n\t}"
                : "=r"(done) : "r"(mb), "r"(ph) : "memory");
            while (!done) {
                asm volatile(
                    "{\n\t.reg .pred p;\n\t"
                    "mbarrier.try_wait.parity.acquire.cta.shared::cta.b64 p, [%1], %2, 0x989680;\n\t"
                    "selp.b32 %0, 1, 0, p;\n\t}"
                    : "=r"(done) : "r"(mb), "r"(ph) : "memory");
            }
        }

        // ---- compute case c0+it from stage st ----
        float Fx = 0.f, Fy = 0.f, d3 = 0.f, d4 = 0.f;
        #pragma unroll
        for (int k = 0; k < 3; k++) {
            int j = t + k * 128;
            bool valid = (k < 2) || (t < NODES - 256);
            if (valid) {
                int jp  = (j + 1 == NODES) ? 0 : j + 1;
                int jpp = (jp + 1 == NODES) ? 0 : jp + 1;
                float2 a  = s_crd[st][j];
                float2 b  = s_crd[st][jp];
                float2 cn = s_crd[st][jpp];
                float2 a1 = s_crd[st][NODES + j];
                float2 b1 = s_crd[st][NODES + jp];
                float4 f0  = s_fld[st][j];
                float4 f1  = s_fld[st][NODES + j];
                float4 f1p = s_fld[st][NODES + jp];

                float tx = b.x - a.x, ty = b.y - a.y;
                float tn = sqrtf(tx * tx + ty * ty);
                float dx = a1.x - a.x, dy = a1.y - a.y;
                float dl = sqrtf(dx * dx + dy * dy);
                float tau0 = MIU_F * ((f1.z * tx + f1.w * ty) / tn) / dl;

                float tx1 = cn.x - b.x, ty1 = cn.y - b.y;
                float tn1 = sqrtf(tx1 * tx1 + ty1 * ty1);
                float dx1 = b1.x - b.x, dy1 = b1.y - b.y;
                float dl1 = sqrtf(dx1 * dx1 + dy1 * dy1);
                float tau1 = MIU_F * ((f1p.z * tx1 + f1p.w * ty1) / tn1) / dl1;

                float ta = 0.5f * (tau0 + tau1);
                float pt = f0.x;
                Fx += -pt * ty + 50.f * ta * tx;
                Fy +=  pt * tx + 50.f * ta * ty;
                d3 += s_dsg[st][5 * j + 3];
                d4 += s_dsg[st][5 * j + 4];
            }
        }

        #pragma unroll
        for (int off = 16; off; off >>= 1) {
            Fx += __shfl_down_sync(FULL, Fx, off);
            Fy += __shfl_down_sync(FULL, Fy, off);
            d3 += __shfl_down_sync(FULL, d3, off);
            d4 += __shfl_down_sync(FULL, d4, off);
        }
        int warp = t >> 5, lane = t & 31;
        if (lane == 0) {
            s_red[st][warp][0] = Fx;
            s_red[st][warp][1] = Fy;
            s_red[st][warp][2] = d3;
            s_red[st][warp][3] = d4;
        }
        __syncthreads();   // all reads of stage st done; s_red[st] visible

        if (t == 0) {
            if (it + 2 < CPB) issue(st, it + 2);   // refill freed stage ASAP
            float fx = 0.f, fy = 0.f, s3 = 0.f, s4 = 0.f;
            #pragma unroll
            for (int w = 0; w < 4; w++) {
                fx += s_red[st][w][0];
                fy += s_red[st][w][1];
                s3 += s_red[st][w][2];
                s4 += s_red[st][w][3];
            }
            float Ma = s3 * (0.3f / (float)NODES) + 0.3f;
            float af = s4 * (ALPHA_F / (float)NODES);
            float ca = cosf(af), sa = sinf(af);
            float Fxn = fx * ca + fy * sa;
            float Fyn = fy * ca - Fxn * sa;   // reference uses Fx_new (literal)
            float q = QCOEF_F * Ma * Ma;
            out[c0 + it] = make_float2(Fxn / q, Fyn / q);
        }
    }
}

extern "C" void kernel_launch(void* const* d_in, const int* in_sizes, int n_in,
                              void* d_out, int out_size) {
    // metadata order: batch(int32), coords(f32), fields(f32), design(f32), num_case, nodes_num
    const float* coords = (const float*)d_in[1];
    const float* fields = (const float*)d_in[2];
    const float* design = (const float*)d_in[3];
    float2* out = (float2*)d_out;
    dyn_kernel<<<GRID, 128>>>(coords, fields, design, out);
}